// round 1
// baseline (speedup 1.0000x reference)
#include <cuda_runtime.h>
#include <cstdint>

#define SEQ  4096
#define HID  1024
#define NCLS 256

// ---------------- scratch (device globals: allocation-free) ----------------
__device__ float g_table[NCLS * 4 * HID];   //  4 MB  pre-activation table for layer0
__device__ float g_pre1 [SEQ  * 4 * HID];   // 64 MB  pre for layer1
__device__ float g_pre2 [SEQ  * 4 * NCLS];  // 16 MB  pre for layer2
__device__ float g_hs0  [SEQ * HID];        // 16 MB
__device__ float g_hs1  [SEQ * HID];        // 16 MB
__device__ float g_cfin [2 * HID + NCLS];   // c0, c1, c2 finals
__device__ int   g_ctr  [3 * SEQ];          // per-step sync counters per layer

// ---------------- helpers ----------------
__device__ __forceinline__ int ldacq(const int* p) {
    int v;
    asm volatile("ld.acquire.gpu.global.b32 %0, [%1];" : "=r"(v) : "l"(p) : "memory");
    return v;
}
__device__ __forceinline__ float fsig(float x) {
    return __fdividef(1.0f, 1.0f + __expf(-x));
}
__device__ __forceinline__ float ftanh(float x) {
    float a = fabsf(x);
    float e = __expf(2.0f * a);
    float r = 1.0f - __fdividef(2.0f, e + 1.0f);   // (e-1)/(e+1), overflow-safe
    return copysignf(r, x);
}

// ---------------- zero the sync counters (every launch / graph replay) -----
__global__ void zero_ctr_kernel() {
    int i = blockIdx.x * blockDim.x + threadIdx.x;
    if (i < 3 * SEQ) g_ctr[i] = 0;
}

// ---------------- GEMM:  C[M][N] = A[M][K] @ B[N][K]^T + b1[N] + b2[N] -----
// WHICH selects A and C from device globals (0: table, 1: pre1, 2: pre2)
template<int WHICH>
__global__ void __launch_bounds__(256)
gemm_bias(const float* __restrict__ Ain, const float* __restrict__ B,
          const float* __restrict__ b1, const float* __restrict__ b2,
          int M, int N, int K)
{
    const float* A = (WHICH == 1) ? g_hs0 : (WHICH == 2) ? g_hs1 : Ain;
    float*       C = (WHICH == 0) ? g_table : (WHICH == 1) ? g_pre1 : g_pre2;

    __shared__ float As[16][68];
    __shared__ float Bs[16][68];

    const int m0 = blockIdx.y * 64;
    const int n0 = blockIdx.x * 64;
    const int tid = threadIdx.x;
    const int tm = tid >> 4;        // 0..15
    const int tn = tid & 15;        // 0..15
    const int lr = tid >> 2;        // 0..63 row of tile being loaded
    const int lk = (tid & 3) * 4;   // k offset within 16

    float acc[4][4];
#pragma unroll
    for (int i = 0; i < 4; i++)
#pragma unroll
        for (int j = 0; j < 4; j++) acc[i][j] = 0.0f;

    for (int kt = 0; kt < K; kt += 16) {
        float4 av = *reinterpret_cast<const float4*>(&A[(size_t)(m0 + lr) * K + kt + lk]);
        float4 bv = *reinterpret_cast<const float4*>(&B[(size_t)(n0 + lr) * K + kt + lk]);
        __syncthreads();
        As[lk + 0][lr] = av.x; As[lk + 1][lr] = av.y; As[lk + 2][lr] = av.z; As[lk + 3][lr] = av.w;
        Bs[lk + 0][lr] = bv.x; Bs[lk + 1][lr] = bv.y; Bs[lk + 2][lr] = bv.z; Bs[lk + 3][lr] = bv.w;
        __syncthreads();
#pragma unroll
        for (int kk = 0; kk < 16; kk++) {
            float4 a4 = *reinterpret_cast<const float4*>(&As[kk][tm * 4]);
            float4 b4 = *reinterpret_cast<const float4*>(&Bs[kk][tn * 4]);
            float a[4] = {a4.x, a4.y, a4.z, a4.w};
            float b[4] = {b4.x, b4.y, b4.z, b4.w};
#pragma unroll
            for (int i = 0; i < 4; i++)
#pragma unroll
                for (int j = 0; j < 4; j++) acc[i][j] += a[i] * b[j];
        }
    }

    const int col0 = n0 + tn * 4;
    float4 v1 = *reinterpret_cast<const float4*>(&b1[col0]);
    float4 v2 = *reinterpret_cast<const float4*>(&b2[col0]);
    float bias[4] = {v1.x + v2.x, v1.y + v2.y, v1.z + v2.z, v1.w + v2.w};
#pragma unroll
    for (int i = 0; i < 4; i++) {
        int row = m0 + tm * 4 + i;
        float4 o;
        o.x = acc[i][0] + bias[0];
        o.y = acc[i][1] + bias[1];
        o.z = acc[i][2] + bias[2];
        o.w = acc[i][3] + bias[3];
        *reinterpret_cast<float4*>(&C[(size_t)row * N + col0]) = o;
    }
}

// ---------------- LSTM scan ----------------
// OUTDIM outputs split across NCTA = OUTDIM/8 CTAs, 8 outputs (32 gate rows) each.
// 8 warps per CTA; warp w covers h-chunk [w*CHUNK, w*CHUNK+CHUNK); lane l owns row l.
// Weights are register-resident (CHUNK floats per lane).
template<int INDIM, int OUTDIM, int LAYER>
__global__ void __launch_bounds__(256, 1)
lstm_scan(const float* __restrict__ whh,       // [4*OUTDIM][INDIM]
          const int*   __restrict__ tokens,    // layer 0 only
          float*       hs_param)               // layer 2 only (d_out)
{
    constexpr bool TABLE = (LAYER == 0);
    constexpr int  NCTA  = OUTDIM / 8;
    constexpr int  CHUNK = INDIM / 8;
    constexpr int  W4    = CHUNK / 4;

    const float* pre = (LAYER == 0) ? g_table : (LAYER == 1) ? g_pre1 : g_pre2;
    float* hs  = (LAYER == 0) ? g_hs0 : (LAYER == 1) ? g_hs1 : hs_param;
    float* cf  = g_cfin + ((LAYER == 0) ? 0 : (LAYER == 1) ? HID : 2 * HID);
    int*   ctr = g_ctr + LAYER * SEQ;

    const int tid = threadIdx.x;
    const int w = tid >> 5;
    const int l = tid & 31;
    const int cta = blockIdx.x;
    const int rowg = (l >> 3) * OUTDIM + cta * 8 + (l & 7);   // global gate row

    __shared__ float4 shh[INDIM / 4];
    __shared__ float  partial[2][8][33];
    __shared__ int    stok[TABLE ? SEQ : 1];

    // load this lane's weights into registers
    float4 wr[W4];
    {
        const float4* wp = reinterpret_cast<const float4*>(whh + (size_t)rowg * INDIM + w * CHUNK);
#pragma unroll
        for (int i = 0; i < W4; i++) wr[i] = __ldg(&wp[i]);
    }
    if constexpr (TABLE) {
        for (int i = tid; i < SEQ; i += 256) stok[i] = tokens[i];
    }
    if (tid < INDIM / 4) shh[tid] = make_float4(0.f, 0.f, 0.f, 0.f);
    __syncthreads();

    auto loadpre = [&](int tt) -> float {
        if constexpr (TABLE)
            return __ldg(pre + (size_t)stok[tt] * (4 * OUTDIM) + rowg);
        else
            return __ldg(pre + (size_t)tt * (4 * OUTDIM) + rowg);
    };

    float c = 0.0f;                           // meaningful for warp 0, lanes 0..7
    float pv = (w == 0) ? loadpre(0) : 0.0f;  // prefetched pre-activation, step 0
    int buf = 0;

    for (int t = 0; t < SEQ; t++) {
        // prefetch next step's pre value (overlaps everything below)
        float pv_next = 0.0f;
        if (w == 0 && t + 1 < SEQ) pv_next = loadpre(t + 1);

        if (t > 0) {
            if (l == 0) {
                while (ldacq(&ctr[t - 1]) < NCTA) { }
            }
            __syncwarp();
            if (l < W4) {
                const float4* hp =
                    reinterpret_cast<const float4*>(hs + (size_t)(t - 1) * OUTDIM + w * CHUNK);
                shh[w * W4 + l] = hp[l];
            }
            __syncwarp();
        }

        // 32 gate-row partial dots, weights from registers, h broadcast from SMEM
        float4 acc = make_float4(0.f, 0.f, 0.f, 0.f);
#pragma unroll
        for (int i = 0; i < W4; i++) {
            float4 hv = shh[w * W4 + i];
            acc.x += wr[i].x * hv.x;
            acc.y += wr[i].y * hv.y;
            acc.z += wr[i].z * hv.z;
            acc.w += wr[i].w * hv.w;
        }
        partial[buf][w][l] = (acc.x + acc.y) + (acc.z + acc.w);
        __syncthreads();

        if (w == 0) {
            float g = pv;
#pragma unroll
            for (int p = 0; p < 8; p++) g += partial[buf][p][l];
            // gates: rows l = gate*8 + out ; gather per-output gate values
            int jj = l & 7;
            float gi = __shfl_sync(0xffffffffu, g, jj);
            float gf = __shfl_sync(0xffffffffu, g, 8 + jj);
            float gg = __shfl_sync(0xffffffffu, g, 16 + jj);
            float go = __shfl_sync(0xffffffffu, g, 24 + jj);
            if (l < 8) {
                c = fsig(gf) * c + fsig(gi) * ftanh(gg);
                float h = fsig(go) * ftanh(c);
                hs[(size_t)t * OUTDIM + cta * 8 + l] = h;
                if (t == SEQ - 1) cf[cta * 8 + l] = c;
            }
            __threadfence();
            __syncwarp();
            if (l == 0) atomicAdd(&ctr[t], 1);
        }
        pv = pv_next;
        buf ^= 1;
    }
}

// ---------------- final output assembly ----------------
__global__ void finalize_kernel(float* __restrict__ out) {
    int i = blockIdx.x * blockDim.x + threadIdx.x;
    const int OB = SEQ * NCLS;   // 1048576: start of h_stack
    if (i < 1024)      out[OB + i] = g_hs0[(SEQ - 1) * HID + i];
    else if (i < 2048) out[OB + i] = g_hs1[(SEQ - 1) * HID + (i - 1024)];
    else if (i < 3072) out[OB + i] = g_cfin[i - 2048];                 // c0
    else if (i < 4096) out[OB + i] = g_cfin[HID + (i - 3072)];         // c1
    else if (i < 4352) out[OB + i] = out[(SEQ - 1) * NCLS + (i - 4096)]; // h2
    else if (i < 4608) out[OB + i] = g_cfin[2 * HID + (i - 4352)];     // c2
}

// ---------------- launch ----------------
extern "C" void kernel_launch(void* const* d_in, const int* in_sizes, int n_in,
                              void* d_out, int out_size)
{
    const int*   tokens = (const int*)  d_in[0];
    const float* embed  = (const float*)d_in[1];
    const float* w_ih0  = (const float*)d_in[2];
    const float* w_hh0  = (const float*)d_in[3];
    const float* b_ih0  = (const float*)d_in[4];
    const float* b_hh0  = (const float*)d_in[5];
    const float* w_ih1  = (const float*)d_in[6];
    const float* w_hh1  = (const float*)d_in[7];
    const float* b_ih1  = (const float*)d_in[8];
    const float* b_hh1  = (const float*)d_in[9];
    const float* w_ih2  = (const float*)d_in[10];
    const float* w_hh2  = (const float*)d_in[11];
    const float* b_ih2  = (const float*)d_in[12];
    const float* b_hh2  = (const float*)d_in[13];
    float* out = (float*)d_out;

    zero_ctr_kernel<<<(3 * SEQ + 255) / 256, 256>>>();

    // layer 0 pre-activation table: [256 classes][4096 rows]
    gemm_bias<0><<<dim3(4 * HID / 64, NCLS / 64), 256>>>(embed, w_ih0, b_ih0, b_hh0,
                                                         NCLS, 4 * HID, HID);
    lstm_scan<HID, HID, 0><<<HID / 8, 256>>>(w_hh0, tokens, nullptr);

    gemm_bias<1><<<dim3(4 * HID / 64, SEQ / 64), 256>>>(nullptr, w_ih1, b_ih1, b_hh1,
                                                        SEQ, 4 * HID, HID);
    lstm_scan<HID, HID, 1><<<HID / 8, 256>>>(w_hh1, nullptr, nullptr);

    gemm_bias<2><<<dim3(4 * NCLS / 64, SEQ / 64), 256>>>(nullptr, w_ih2, b_ih2, b_hh2,
                                                         SEQ, 4 * NCLS, HID);
    lstm_scan<NCLS, NCLS, 2><<<NCLS / 8, 256>>>(w_hh2, nullptr, out);

    finalize_kernel<<<18, 256>>>(out);
}

// round 2
// speedup vs baseline: 1.5738x; 1.5738x over previous
#include <cuda_runtime.h>
#include <cstdint>

#define SEQ  4096
#define HID  1024
#define NCLS 256

typedef unsigned long long ull;

// ---------------- scratch (device globals: allocation-free) ----------------
__device__ float g_table[NCLS * 4 * HID];   //  4 MB  pre-activation table for layer0
__device__ float g_pre1 [SEQ  * 4 * HID];   // 64 MB  pre for layer1
__device__ float g_pre2 [SEQ  * 4 * NCLS];  // 16 MB  pre for layer2
__device__ float g_hs0  [SEQ * HID];        // 16 MB  plain h (GEMM input / finals)
__device__ float g_hs1  [SEQ * HID];        // 16 MB
__device__ ull   g_tg0  [SEQ * HID];        // 32 MB  tagged h for recurrence handoff
__device__ ull   g_tg1  [SEQ * HID];        // 32 MB
__device__ ull   g_tg2  [SEQ * NCLS];       //  8 MB
__device__ float g_cfin [2 * HID + NCLS];   // c0, c1, c2 finals
__device__ unsigned int g_gen;              // per-launch generation for tags

// ---------------- helpers ----------------
__device__ __forceinline__ float fsig(float x) {
    return __fdividef(1.0f, 1.0f + __expf(-x));
}
__device__ __forceinline__ float ftanh(float x) {
    float a = fabsf(x);
    float e = __expf(2.0f * a);
    float r = 1.0f - __fdividef(2.0f, e + 1.0f);   // (e-1)/(e+1), overflow-safe
    return copysignf(r, x);
}
__device__ __forceinline__ ull ld_tag(const ull* p) {
    ull v;
    asm volatile("ld.relaxed.gpu.global.b64 %0, [%1];" : "=l"(v) : "l"(p) : "memory");
    return v;
}
__device__ __forceinline__ void st_tag(ull* p, ull v) {
    asm volatile("st.relaxed.gpu.global.b64 [%0], %1;" :: "l"(p), "l"(v) : "memory");
}
// packed dual-fp32 FMA (B300 f32x2 pipe, rt 1 vs 2 for FFMA-3reg)
__device__ __forceinline__ ull fma2(ull a, ull b, ull c) {
    ull d;
    asm("fma.rn.f32x2 %0, %1, %2, %3;" : "=l"(d) : "l"(a), "l"(b), "l"(c));
    return d;
}
__device__ __forceinline__ float lo32(ull v) { return __uint_as_float((unsigned)v); }
__device__ __forceinline__ float hi32(ull v) { return __uint_as_float((unsigned)(v >> 32)); }

__global__ void bump_gen_kernel() { if (threadIdx.x == 0) g_gen += 1u; }

// ---------------- GEMM:  C[M][N] = A[M][K] @ B[N][K]^T + b1[N] + b2[N] -----
template<int WHICH>
__global__ void __launch_bounds__(256)
gemm_bias(const float* __restrict__ Ain, const float* __restrict__ B,
          const float* __restrict__ b1, const float* __restrict__ b2,
          int M, int N, int K)
{
    const float* A = (WHICH == 1) ? g_hs0 : (WHICH == 2) ? g_hs1 : Ain;
    float*       C = (WHICH == 0) ? g_table : (WHICH == 1) ? g_pre1 : g_pre2;

    __shared__ float As[16][68];
    __shared__ float Bs[16][68];

    const int m0 = blockIdx.y * 64;
    const int n0 = blockIdx.x * 64;
    const int tid = threadIdx.x;
    const int tm = tid >> 4;
    const int tn = tid & 15;
    const int lr = tid >> 2;
    const int lk = (tid & 3) * 4;

    float acc[4][4];
#pragma unroll
    for (int i = 0; i < 4; i++)
#pragma unroll
        for (int j = 0; j < 4; j++) acc[i][j] = 0.0f;

    for (int kt = 0; kt < K; kt += 16) {
        float4 av = *reinterpret_cast<const float4*>(&A[(size_t)(m0 + lr) * K + kt + lk]);
        float4 bv = *reinterpret_cast<const float4*>(&B[(size_t)(n0 + lr) * K + kt + lk]);
        __syncthreads();
        As[lk + 0][lr] = av.x; As[lk + 1][lr] = av.y; As[lk + 2][lr] = av.z; As[lk + 3][lr] = av.w;
        Bs[lk + 0][lr] = bv.x; Bs[lk + 1][lr] = bv.y; Bs[lk + 2][lr] = bv.z; Bs[lk + 3][lr] = bv.w;
        __syncthreads();
#pragma unroll
        for (int kk = 0; kk < 16; kk++) {
            float4 a4 = *reinterpret_cast<const float4*>(&As[kk][tm * 4]);
            float4 b4 = *reinterpret_cast<const float4*>(&Bs[kk][tn * 4]);
            float a[4] = {a4.x, a4.y, a4.z, a4.w};
            float b[4] = {b4.x, b4.y, b4.z, b4.w};
#pragma unroll
            for (int i = 0; i < 4; i++)
#pragma unroll
                for (int j = 0; j < 4; j++) acc[i][j] += a[i] * b[j];
        }
    }

    const int col0 = n0 + tn * 4;
    float4 v1 = *reinterpret_cast<const float4*>(&b1[col0]);
    float4 v2 = *reinterpret_cast<const float4*>(&b2[col0]);
    float bias[4] = {v1.x + v2.x, v1.y + v2.y, v1.z + v2.z, v1.w + v2.w};
#pragma unroll
    for (int i = 0; i < 4; i++) {
        int row = m0 + tm * 4 + i;
        float4 o;
        o.x = acc[i][0] + bias[0];
        o.y = acc[i][1] + bias[1];
        o.z = acc[i][2] + bias[2];
        o.w = acc[i][3] + bias[3];
        *reinterpret_cast<float4*>(&C[(size_t)row * N + col0]) = o;
    }
}

// ---------------- LSTM scan (warp-per-output, tagged handoff) ----------------
// 8 warps/CTA, warp w owns output (cta*8+w) = 4 gate rows.
// Lane l covers k = 4*l + 128*i; weights register-resident (4 rows x INDIM/32).
// h_{t-1} handoff: 64-bit {tag,h} words in L2, polled directly (no counters).
template<int INDIM, int OUTDIM, int LAYER>
__global__ void __launch_bounds__(256, 1)
lstm_scan(const float* __restrict__ whh,       // [4*OUTDIM][INDIM]
          const int*   __restrict__ tokens,    // layer 0 only
          float*       __restrict__ hs_param)  // layer 2: d_out
{
    constexpr int KITER = INDIM / 128;   // 8 (HID) or 2 (NCLS)
    constexpr int PPT   = INDIM / 256;   // tagged pairs staged per thread

    const float* pre = (LAYER == 0) ? g_table : (LAYER == 1) ? g_pre1 : g_pre2;
    ull*   tg = (LAYER == 0) ? g_tg0 : (LAYER == 1) ? g_tg1 : g_tg2;
    float* hs = (LAYER == 0) ? g_hs0 : (LAYER == 1) ? g_hs1 : hs_param;
    float* cf = g_cfin + ((LAYER == 0) ? 0 : (LAYER == 1) ? HID : 2 * HID);

    const int tid = threadIdx.x;
    const int w = tid >> 5;
    const int l = tid & 31;
    const int out = blockIdx.x * 8 + w;
    const unsigned tb = g_gen * (unsigned)(SEQ + 1);

    __shared__ __align__(16) float sh[2][INDIM];
    __shared__ int stok[(LAYER == 0) ? SEQ : 1];

    // register-resident weights: 4 gate rows, this lane's k-slices
    ulonglong2 wq[4][KITER];
#pragma unroll
    for (int r = 0; r < 4; r++)
#pragma unroll
        for (int i = 0; i < KITER; i++)
            wq[r][i] = *reinterpret_cast<const ulonglong2*>(
                whh + (size_t)(r * OUTDIM + out) * INDIM + i * 128 + 4 * l);

    if constexpr (LAYER == 0) {
        for (int i = tid; i < SEQ; i += 256) stok[i] = tokens[i];
    }
    for (int i = tid; i < INDIM; i += 256) sh[0][i] = 0.0f;
    __syncthreads();

    auto loadpre = [&](int tt, int r) -> float {
        if constexpr (LAYER == 0)
            return __ldg(&pre[(size_t)stok[tt] * (4 * OUTDIM) + r * OUTDIM + out]);
        else
            return __ldg(&pre[(size_t)tt * (4 * OUTDIM) + r * OUTDIM + out]);
    };

    float c = 0.0f;
    float pv = (l < 4) ? loadpre(0, l) : 0.0f;

    for (int t = 0; t < SEQ; t++) {
        float pvn = (l < 4 && t + 1 < SEQ) ? loadpre(t + 1, l) : 0.0f;

        float* shb = sh[t & 1];
        if (t > 0) {
            const ull* src = tg + (size_t)(t - 1) * INDIM;
            const unsigned expect = tb + (unsigned)t;   // producer wrote tb + (t-1) + 1
#pragma unroll
            for (int j = 0; j < PPT; j++) {
                const int idx = tid + 256 * j;
                ull v;
                do { v = ld_tag(src + idx); } while ((unsigned)(v >> 32) != expect);
                shb[idx] = __uint_as_float((unsigned)v);
            }
        }
        __syncthreads();

        // 4 gate-row dot products, packed f32x2 FMA
        ull acc[4] = {0ull, 0ull, 0ull, 0ull};
#pragma unroll
        for (int i = 0; i < KITER; i++) {
            ulonglong2 hv = *reinterpret_cast<const ulonglong2*>(shb + i * 128 + 4 * l);
#pragma unroll
            for (int r = 0; r < 4; r++) {
                acc[r] = fma2(wq[r][i].x, hv.x, acc[r]);
                acc[r] = fma2(wq[r][i].y, hv.y, acc[r]);
            }
        }
        float g[4];
#pragma unroll
        for (int r = 0; r < 4; r++) g[r] = lo32(acc[r]) + hi32(acc[r]);
#pragma unroll
        for (int s = 16; s > 0; s >>= 1)
#pragma unroll
            for (int r = 0; r < 4; r++) g[r] += __shfl_xor_sync(0xffffffffu, g[r], s);

        const float p0 = __shfl_sync(0xffffffffu, pv, 0);
        const float p1 = __shfl_sync(0xffffffffu, pv, 1);
        const float p2 = __shfl_sync(0xffffffffu, pv, 2);
        const float p3 = __shfl_sync(0xffffffffu, pv, 3);

        c = fsig(g[1] + p1) * c + fsig(g[0] + p0) * ftanh(g[2] + p2);
        const float h = fsig(g[3] + p3) * ftanh(c);

        if (l == 0) {
            const ull vv = ((ull)(tb + (unsigned)t + 1u) << 32) | (ull)__float_as_uint(h);
            st_tag(tg + (size_t)t * OUTDIM + out, vv);
            hs[(size_t)t * OUTDIM + out] = h;
            if (t == SEQ - 1) cf[out] = c;
        }
        pv = pvn;
    }
}

// ---------------- final output assembly ----------------
__global__ void finalize_kernel(float* __restrict__ out) {
    int i = blockIdx.x * blockDim.x + threadIdx.x;
    const int OB = SEQ * NCLS;   // 1048576: start of h_stack
    if (i < 1024)      out[OB + i] = g_hs0[(SEQ - 1) * HID + i];
    else if (i < 2048) out[OB + i] = g_hs1[(SEQ - 1) * HID + (i - 1024)];
    else if (i < 3072) out[OB + i] = g_cfin[i - 2048];                   // c0
    else if (i < 4096) out[OB + i] = g_cfin[HID + (i - 3072)];           // c1
    else if (i < 4352) out[OB + i] = out[(SEQ - 1) * NCLS + (i - 4096)]; // h2
    else if (i < 4608) out[OB + i] = g_cfin[2 * HID + (i - 4352)];       // c2
}

// ---------------- launch ----------------
extern "C" void kernel_launch(void* const* d_in, const int* in_sizes, int n_in,
                              void* d_out, int out_size)
{
    const int*   tokens = (const int*)  d_in[0];
    const float* embed  = (const float*)d_in[1];
    const float* w_ih0  = (const float*)d_in[2];
    const float* w_hh0  = (const float*)d_in[3];
    const float* b_ih0  = (const float*)d_in[4];
    const float* b_hh0  = (const float*)d_in[5];
    const float* w_ih1  = (const float*)d_in[6];
    const float* w_hh1  = (const float*)d_in[7];
    const float* b_ih1  = (const float*)d_in[8];
    const float* b_hh1  = (const float*)d_in[9];
    const float* w_ih2  = (const float*)d_in[10];
    const float* w_hh2  = (const float*)d_in[11];
    const float* b_ih2  = (const float*)d_in[12];
    const float* b_hh2  = (const float*)d_in[13];
    float* out = (float*)d_out;

    bump_gen_kernel<<<1, 32>>>();

    // layer 0 pre-activation table: [256 classes][4096 gate rows]
    gemm_bias<0><<<dim3(4 * HID / 64, NCLS / 64), 256>>>(embed, w_ih0, b_ih0, b_hh0,
                                                         NCLS, 4 * HID, HID);
    lstm_scan<HID, HID, 0><<<HID / 8, 256>>>(w_hh0, tokens, nullptr);

    gemm_bias<1><<<dim3(4 * HID / 64, SEQ / 64), 256>>>(nullptr, w_ih1, b_ih1, b_hh1,
                                                        SEQ, 4 * HID, HID);
    lstm_scan<HID, HID, 1><<<HID / 8, 256>>>(w_hh1, nullptr, nullptr);

    gemm_bias<2><<<dim3(4 * NCLS / 64, SEQ / 64), 256>>>(nullptr, w_ih2, b_ih2, b_hh2,
                                                         SEQ, 4 * NCLS, HID);
    lstm_scan<NCLS, NCLS, 2><<<NCLS / 8, 256>>>(w_hh2, nullptr, out);

    finalize_kernel<<<18, 256>>>(out);
}

// round 3
// speedup vs baseline: 1.6920x; 1.0751x over previous
#include <cuda_runtime.h>
#include <cstdint>

#define SEQ  4096
#define HID  1024
#define NCLS 256

typedef unsigned long long ull;

// ---------------- scratch (device globals: allocation-free) ----------------
__device__ float g_table[NCLS * 4 * HID];   //  4 MB  pre-activation table for layer0
__device__ float g_pre1 [SEQ  * 4 * HID];   // 64 MB  pre for layer1
__device__ float g_pre2 [SEQ  * 4 * NCLS];  // 16 MB  pre for layer2
__device__ float g_hs0  [SEQ * HID];        // 16 MB  plain h (GEMM input / finals)
__device__ float g_hs1  [SEQ * HID];        // 16 MB
__device__ ull   g_tg0  [SEQ * HID];        // 32 MB  tagged h for recurrence handoff
__device__ ull   g_tg1  [SEQ * HID];        // 32 MB
__device__ ull   g_tg2  [SEQ * NCLS];       //  8 MB
__device__ float g_cfin [2 * HID + NCLS];   // c0, c1, c2 finals
__device__ unsigned int g_gen;              // per-launch generation for tags

// ---------------- helpers ----------------
__device__ __forceinline__ float fsig(float x) {
    return __fdividef(1.0f, 1.0f + __expf(-x));
}
__device__ __forceinline__ float ftanh(float x) {
    float a = fabsf(x);
    float e = __expf(2.0f * a);
    float r = 1.0f - __fdividef(2.0f, e + 1.0f);   // (e-1)/(e+1), overflow-safe
    return copysignf(r, x);
}
__device__ __forceinline__ ull ld_tag(const ull* p) {
    ull v;
    asm volatile("ld.relaxed.gpu.global.b64 %0, [%1];" : "=l"(v) : "l"(p) : "memory");
    return v;
}
__device__ __forceinline__ void st_tag(ull* p, ull v) {
    asm volatile("st.relaxed.gpu.global.b64 [%0], %1;" :: "l"(p), "l"(v) : "memory");
}
// packed dual-fp32 FMA (B300 f32x2 pipe)
__device__ __forceinline__ ull fma2(ull a, ull b, ull c) {
    ull d;
    asm("fma.rn.f32x2 %0, %1, %2, %3;" : "=l"(d) : "l"(a), "l"(b), "l"(c));
    return d;
}
__device__ __forceinline__ float lo32(ull v) { return __uint_as_float((unsigned)v); }
__device__ __forceinline__ float hi32(ull v) { return __uint_as_float((unsigned)(v >> 32)); }

__global__ void bump_gen_kernel() { if (threadIdx.x == 0) g_gen += 1u; }

// ---------------- GEMM:  C[M][N] = A[M][K] @ B[N][K]^T + b1[N] + b2[N] -----
// 128x64 tile, 256 threads, 8x4 accumulators per thread, K-tile 16.
template<int WHICH>
__global__ void __launch_bounds__(256)
gemm_bias(const float* __restrict__ Ain, const float* __restrict__ B,
          const float* __restrict__ b1, const float* __restrict__ b2,
          int M, int N, int K)
{
    const float* A = (WHICH == 1) ? g_hs0 : (WHICH == 2) ? g_hs1 : Ain;
    float*       C = (WHICH == 0) ? g_table : (WHICH == 1) ? g_pre1 : g_pre2;

    __shared__ float As[16][136];
    __shared__ float Bs[16][72];

    const int m0 = blockIdx.y * 128;
    const int n0 = blockIdx.x * 64;
    const int tid = threadIdx.x;
    const int tm = tid >> 4;          // 0..15 -> 8 rows each
    const int tn = tid & 15;          // 0..15 -> 4 cols each
    const int lra = tid >> 1;         // 0..127  A row being loaded
    const int lka = (tid & 1) * 8;    // 0 or 8  A k-offset (2 float4s)
    const int lrb = tid >> 2;         // 0..63   B row being loaded
    const int lkb = (tid & 3) * 4;    // B k-offset

    float acc[8][4];
#pragma unroll
    for (int i = 0; i < 8; i++)
#pragma unroll
        for (int j = 0; j < 4; j++) acc[i][j] = 0.0f;

    for (int kt = 0; kt < K; kt += 16) {
        float4 a0 = *reinterpret_cast<const float4*>(&A[(size_t)(m0 + lra) * K + kt + lka]);
        float4 a1 = *reinterpret_cast<const float4*>(&A[(size_t)(m0 + lra) * K + kt + lka + 4]);
        float4 bv = *reinterpret_cast<const float4*>(&B[(size_t)(n0 + lrb) * K + kt + lkb]);
        __syncthreads();
        As[lka + 0][lra] = a0.x; As[lka + 1][lra] = a0.y; As[lka + 2][lra] = a0.z; As[lka + 3][lra] = a0.w;
        As[lka + 4][lra] = a1.x; As[lka + 5][lra] = a1.y; As[lka + 6][lra] = a1.z; As[lka + 7][lra] = a1.w;
        Bs[lkb + 0][lrb] = bv.x; Bs[lkb + 1][lrb] = bv.y; Bs[lkb + 2][lrb] = bv.z; Bs[lkb + 3][lrb] = bv.w;
        __syncthreads();
#pragma unroll
        for (int kk = 0; kk < 16; kk++) {
            float4 a4 = *reinterpret_cast<const float4*>(&As[kk][tm * 8]);
            float4 a5 = *reinterpret_cast<const float4*>(&As[kk][tm * 8 + 4]);
            float4 b4 = *reinterpret_cast<const float4*>(&Bs[kk][tn * 4]);
            float a[8] = {a4.x, a4.y, a4.z, a4.w, a5.x, a5.y, a5.z, a5.w};
            float b[4] = {b4.x, b4.y, b4.z, b4.w};
#pragma unroll
            for (int i = 0; i < 8; i++)
#pragma unroll
                for (int j = 0; j < 4; j++) acc[i][j] += a[i] * b[j];
        }
    }

    const int col0 = n0 + tn * 4;
    float4 v1 = *reinterpret_cast<const float4*>(&b1[col0]);
    float4 v2 = *reinterpret_cast<const float4*>(&b2[col0]);
    float bias[4] = {v1.x + v2.x, v1.y + v2.y, v1.z + v2.z, v1.w + v2.w};
#pragma unroll
    for (int i = 0; i < 8; i++) {
        int row = m0 + tm * 8 + i;
        float4 o;
        o.x = acc[i][0] + bias[0];
        o.y = acc[i][1] + bias[1];
        o.z = acc[i][2] + bias[2];
        o.w = acc[i][3] + bias[3];
        *reinterpret_cast<float4*>(&C[(size_t)row * N + col0]) = o;
    }
}

// ---------------- LSTM scan (warp-per-output, tagged handoff) ----------------
// 8 warps/CTA, warp w owns output (cta*8+w) = 4 gate rows.
// Lane l covers k = 4*l + 128*i; weights register-resident.
// h_{t-1} handoff: 64-bit {tag,h} words in L2, polled in PARALLEL (batch of PPT).
template<int INDIM, int OUTDIM, int LAYER>
__global__ void __launch_bounds__(256, 1)
lstm_scan(const float* __restrict__ whh,       // [4*OUTDIM][INDIM]
          const int*   __restrict__ tokens,    // layer 0 only
          float*       __restrict__ hs_param)  // layer 2: d_out
{
    constexpr int KITER = INDIM / 128;   // 8 (HID) or 2 (NCLS)
    constexpr int PPT   = INDIM / 256;   // tagged words staged per thread

    const float* pre = (LAYER == 0) ? g_table : (LAYER == 1) ? g_pre1 : g_pre2;
    ull*   tg = (LAYER == 0) ? g_tg0 : (LAYER == 1) ? g_tg1 : g_tg2;
    float* hs = (LAYER == 0) ? g_hs0 : (LAYER == 1) ? g_hs1 : hs_param;
    float* cf = g_cfin + ((LAYER == 0) ? 0 : (LAYER == 1) ? HID : 2 * HID);

    const int tid = threadIdx.x;
    const int w = tid >> 5;
    const int l = tid & 31;
    const int out = blockIdx.x * 8 + w;
    const unsigned tb = g_gen * (unsigned)(SEQ + 1);

    __shared__ __align__(16) float sh[2][INDIM];
    __shared__ int stok[(LAYER == 0) ? SEQ : 1];

    // register-resident weights: 4 gate rows, this lane's k-slices
    ulonglong2 wq[4][KITER];
#pragma unroll
    for (int r = 0; r < 4; r++)
#pragma unroll
        for (int i = 0; i < KITER; i++)
            wq[r][i] = *reinterpret_cast<const ulonglong2*>(
                whh + (size_t)(r * OUTDIM + out) * INDIM + i * 128 + 4 * l);

    if constexpr (LAYER == 0) {
        for (int i = tid; i < SEQ; i += 256) stok[i] = tokens[i];
    }
    for (int i = tid; i < INDIM; i += 256) sh[0][i] = 0.0f;
    __syncthreads();

    auto loadpre = [&](int tt, int r) -> float {
        if constexpr (LAYER == 0)
            return __ldg(&pre[(size_t)stok[tt] * (4 * OUTDIM) + r * OUTDIM + out]);
        else
            return __ldg(&pre[(size_t)tt * (4 * OUTDIM) + r * OUTDIM + out]);
    };

    float c = 0.0f;
    float pv = (l < 4) ? loadpre(0, l) : 0.0f;

    for (int t = 0; t < SEQ; t++) {
        float pvn = (l < 4 && t + 1 < SEQ) ? loadpre(t + 1, l) : 0.0f;

        float* shb = sh[t & 1];
        if (t > 0) {
            const ull* src = tg + (size_t)(t - 1) * INDIM;
            const unsigned expect = tb + (unsigned)t;   // producer wrote tb + (t-1) + 1
            ull v[PPT];
            // parallel batch poll: all PPT loads in flight simultaneously
#pragma unroll
            for (int j = 0; j < PPT; j++) v[j] = ld_tag(src + tid + 256 * j);
            while (true) {
                bool ok = true;
#pragma unroll
                for (int j = 0; j < PPT; j++) ok &= ((unsigned)(v[j] >> 32) == expect);
                if (ok) break;
#pragma unroll
                for (int j = 0; j < PPT; j++) v[j] = ld_tag(src + tid + 256 * j);
            }
#pragma unroll
            for (int j = 0; j < PPT; j++)
                shb[tid + 256 * j] = __uint_as_float((unsigned)v[j]);
        }
        __syncthreads();

        // 4 gate-row dot products, packed f32x2 FMA
        ull acc[4] = {0ull, 0ull, 0ull, 0ull};
#pragma unroll
        for (int i = 0; i < KITER; i++) {
            ulonglong2 hv = *reinterpret_cast<const ulonglong2*>(shb + i * 128 + 4 * l);
#pragma unroll
            for (int r = 0; r < 4; r++) {
                acc[r] = fma2(wq[r][i].x, hv.x, acc[r]);
                acc[r] = fma2(wq[r][i].y, hv.y, acc[r]);
            }
        }
        float g[4];
#pragma unroll
        for (int r = 0; r < 4; r++) g[r] = lo32(acc[r]) + hi32(acc[r]);
#pragma unroll
        for (int s = 16; s > 0; s >>= 1)
#pragma unroll
            for (int r = 0; r < 4; r++) g[r] += __shfl_xor_sync(0xffffffffu, g[r], s);

        const float p0 = __shfl_sync(0xffffffffu, pv, 0);
        const float p1 = __shfl_sync(0xffffffffu, pv, 1);
        const float p2 = __shfl_sync(0xffffffffu, pv, 2);
        const float p3 = __shfl_sync(0xffffffffu, pv, 3);

        c = fsig(g[1] + p1) * c + fsig(g[0] + p0) * ftanh(g[2] + p2);
        const float h = fsig(g[3] + p3) * ftanh(c);

        if (l == 0) {
            const ull vv = ((ull)(tb + (unsigned)t + 1u) << 32) | (ull)__float_as_uint(h);
            st_tag(tg + (size_t)t * OUTDIM + out, vv);
            hs[(size_t)t * OUTDIM + out] = h;
            if (t == SEQ - 1) cf[out] = c;
        }
        pv = pvn;
    }
}

// ---------------- final output assembly ----------------
__global__ void finalize_kernel(float* __restrict__ out) {
    int i = blockIdx.x * blockDim.x + threadIdx.x;
    const int OB = SEQ * NCLS;   // 1048576: start of h_stack
    if (i < 1024)      out[OB + i] = g_hs0[(SEQ - 1) * HID + i];
    else if (i < 2048) out[OB + i] = g_hs1[(SEQ - 1) * HID + (i - 1024)];
    else if (i < 3072) out[OB + i] = g_cfin[i - 2048];                   // c0
    else if (i < 4096) out[OB + i] = g_cfin[HID + (i - 3072)];           // c1
    else if (i < 4352) out[OB + i] = out[(SEQ - 1) * NCLS + (i - 4096)]; // h2
    else if (i < 4608) out[OB + i] = g_cfin[2 * HID + (i - 4352)];       // c2
}

// ---------------- launch ----------------
extern "C" void kernel_launch(void* const* d_in, const int* in_sizes, int n_in,
                              void* d_out, int out_size)
{
    const int*   tokens = (const int*)  d_in[0];
    const float* embed  = (const float*)d_in[1];
    const float* w_ih0  = (const float*)d_in[2];
    const float* w_hh0  = (const float*)d_in[3];
    const float* b_ih0  = (const float*)d_in[4];
    const float* b_hh0  = (const float*)d_in[5];
    const float* w_ih1  = (const float*)d_in[6];
    const float* w_hh1  = (const float*)d_in[7];
    const float* b_ih1  = (const float*)d_in[8];
    const float* b_hh1  = (const float*)d_in[9];
    const float* w_ih2  = (const float*)d_in[10];
    const float* w_hh2  = (const float*)d_in[11];
    const float* b_ih2  = (const float*)d_in[12];
    const float* b_hh2  = (const float*)d_in[13];
    float* out = (float*)d_out;

    bump_gen_kernel<<<1, 32>>>();

    // layer 0 pre-activation table: [256 classes][4096 gate rows]
    gemm_bias<0><<<dim3(4 * HID / 64, NCLS / 128), 256>>>(embed, w_ih0, b_ih0, b_hh0,
                                                          NCLS, 4 * HID, HID);
    lstm_scan<HID, HID, 0><<<HID / 8, 256>>>(w_hh0, tokens, nullptr);

    gemm_bias<1><<<dim3(4 * HID / 64, SEQ / 128), 256>>>(nullptr, w_ih1, b_ih1, b_hh1,
                                                         SEQ, 4 * HID, HID);
    lstm_scan<HID, HID, 1><<<HID / 8, 256>>>(w_hh1, nullptr, nullptr);

    gemm_bias<2><<<dim3(4 * NCLS / 64, SEQ / 128), 256>>>(nullptr, w_ih2, b_ih2, b_hh2,
                                                          SEQ, 4 * NCLS, HID);
    lstm_scan<NCLS, NCLS, 2><<<NCLS / 8, 256>>>(w_hh2, nullptr, out);

    finalize_kernel<<<18, 256>>>(out);
}